// round 14
// baseline (speedup 1.0000x reference)
#include <cuda_runtime.h>
#include <cuda_fp16.h>
#include <cstdint>

#define NT 6144
#define KIN 256
#define DM 128
#define NH 4
#define HD 32
#define NSLICE 3
#define SLICE_KEYS (NT / NSLICE)   // 2048
#define BM 64
#define BNO 128                    // outer key tile (2 inner halves of 64)
#define NKT2 (SLICE_KEYS / BNO)    // 16 outer tiles

#define C1F 0.25502050681732154f   // (1/sqrt(32)) * log2(e)
#define DCUT 1310.0f               // dist*dw cutoff: tail bias >= 13.1 => rel pert <= 1.4e-4

// Scratch (device globals: allocation-free rule)
__device__ __half g_xh[NT * KIN];
__device__ __half g_wht[3 * KIN * DM];      // transposed [w][n][k], Wq pre-scaled by C1F
__device__ __half g_woht[DM * DM];          // Wo transposed [n][k]
__device__ __half g_qh[NT * DM];
__device__ __half g_kh[NT * DM];
__device__ __half g_vh[NT * DM];
__device__ __half g_attp[NSLICE][NT * DM];  // per-slice partial sum(p*v), fp16
__device__ float g_lp[NSLICE][NT * NH];     // per-slice partial sum(p)

// ---------------------------------------------------------------------------
// PTX helpers
// ---------------------------------------------------------------------------
__device__ __forceinline__ uint32_t pack_f16x2(float lo, float hi) {
    uint32_t r; asm("cvt.rn.f16x2.f32 %0, %1, %2;" : "=r"(r) : "f"(hi), "f"(lo)); return r;
}
__device__ __forceinline__ uint32_t ex2_h2(uint32_t a) {
    uint32_t r; asm("ex2.approx.f16x2 %0, %1;" : "=r"(r) : "r"(a)); return r;
}
__device__ __forceinline__ void mma_f16(float d[4], uint32_t a0, uint32_t a1, uint32_t a2, uint32_t a3,
                                        uint32_t b0, uint32_t b1) {
    asm volatile(
        "mma.sync.aligned.m16n8k16.row.col.f32.f16.f16.f32 "
        "{%0,%1,%2,%3}, {%4,%5,%6,%7}, {%8,%9}, {%0,%1,%2,%3};\n"
        : "+f"(d[0]), "+f"(d[1]), "+f"(d[2]), "+f"(d[3])
        : "r"(a0), "r"(a1), "r"(a2), "r"(a3), "r"(b0), "r"(b1));
}
__device__ __forceinline__ void ldsm4(uint32_t r[4], uint32_t addr) {
    asm volatile("ldmatrix.sync.aligned.m8n8.x4.shared.b16 {%0,%1,%2,%3}, [%4];\n"
                 : "=r"(r[0]), "=r"(r[1]), "=r"(r[2]), "=r"(r[3]) : "r"(addr));
}
__device__ __forceinline__ void ldsm4t(uint32_t r[4], uint32_t addr) {
    asm volatile("ldmatrix.sync.aligned.m8n8.x4.trans.shared.b16 {%0,%1,%2,%3}, [%4];\n"
                 : "=r"(r[0]), "=r"(r[1]), "=r"(r[2]), "=r"(r[3]) : "r"(addr));
}
__device__ __forceinline__ void cpa16(uint32_t saddr, const void* gaddr) {
    asm volatile("cp.async.cg.shared.global [%0], [%1], 16;\n" :: "r"(saddr), "l"(gaddr));
}
__device__ __forceinline__ void cpa_commit() { asm volatile("cp.async.commit_group;\n" ::); }
__device__ __forceinline__ void cpa_wait1()  { asm volatile("cp.async.wait_group 1;\n" ::); }

// swizzled byte offset of 16B chunk (row, c) within a [rows][32 half] tile
#define SOFF(r, c) ((uint32_t)((((r) << 2) + ((c) ^ (((r) >> 1) & 3))) << 4))

// ---------------------------------------------------------------------------
// Conversion kernel: x -> fp16; Wq/Wk/Wv -> fp16 transposed (Wq scaled by C1F);
// Wo -> fp16 transposed.
// ---------------------------------------------------------------------------
__global__ __launch_bounds__(256) void convert_kernel(
    const float* __restrict__ x,
    const float* __restrict__ Wq, const float* __restrict__ Wk, const float* __restrict__ Wv,
    const float* __restrict__ Wo)
{
    const int b = blockIdx.x, tid = threadIdx.x;
    if (b < 1536) {
        int base = b * 1024 + tid * 4;
        float4 v = *(const float4*)&x[base];
        *(__half2*)&g_xh[base]     = __floats2half2_rn(v.x, v.y);
        *(__half2*)&g_xh[base + 2] = __floats2half2_rn(v.z, v.w);
    } else if (b < 1584) {
        int bb = b - 1536;              // 0..47
        int w = bb >> 4, part = bb & 15;
        const float* W = (w == 0) ? Wq : (w == 1) ? Wk : Wv;
        float scale = (w == 0) ? C1F : 1.0f;
        __half* dst = g_wht + (size_t)w * (KIN * DM);
#pragma unroll
        for (int i = tid; i < 16 * DM; i += 256) {
            int k = part * 16 + (i >> 7);
            int n = i & 127;
            dst[n * KIN + k] = __float2half(W[k * DM + n] * scale);
        }
    } else {
        int bb = b - 1584;              // 0..15
#pragma unroll
        for (int i = tid; i < 8 * DM; i += 256) {
            int k = bb * 8 + (i >> 7);
            int n = i & 127;
            g_woht[n * DM + k] = __float2half(Wo[k * DM + n]);
        }
    }
}

// ---------------------------------------------------------------------------
// QKV projection GEMM (fp16 mma.sync): C = x @ W + b, output fp16.
// ---------------------------------------------------------------------------
__global__ __launch_bounds__(256, 2) void gemm_qkv_tc(
    const float* __restrict__ bq, const float* __restrict__ bk, const float* __restrict__ bv)
{
    __shared__ __align__(16) __half Xs[2][128 * 32];
    __shared__ __align__(16) __half Ws[2][128 * 32];

    const int tid = threadIdx.x, lane = tid & 31, w = tid >> 5;
    const int y = blockIdx.y;
    const int m0 = blockIdx.x * 128;
    const __half* wht = g_wht + (size_t)y * (KIN * DM);
    const float* bias = (y == 0) ? bq : (y == 1) ? bk : bv;
    const float bscale = (y == 0) ? C1F : 1.0f;
    __half* C = (y == 0) ? g_qh : (y == 1) ? g_kh : g_vh;

    const int lg = lane >> 3, lr = lane & 7;
    const int mg = lane >> 2, mt = lane & 3;

    const uint32_t xs0 = (uint32_t)__cvta_generic_to_shared(Xs);
    const uint32_t ws0 = (uint32_t)__cvta_generic_to_shared(Ws);
    const uint32_t BUF = 128 * 32 * 2;

#pragma unroll
    for (int s = 0; s < 2; ++s) {
#pragma unroll
        for (int r = 0; r < 2; ++r) {
            int id = tid + r * 256;
            int row = id >> 2, c = id & 3;
            cpa16(xs0 + s * BUF + SOFF(row, c), &g_xh[(size_t)(m0 + row) * KIN + s * 32 + c * 8]);
            cpa16(ws0 + s * BUF + SOFF(row, c), &wht[(size_t)row * KIN + s * 32 + c * 8]);
        }
        cpa_commit();
    }

    float Cf[16][4];
#pragma unroll
    for (int f = 0; f < 16; ++f)
#pragma unroll
        for (int r = 0; r < 4; ++r) Cf[f][r] = 0.f;

    uint32_t offA[2], offB[8][2];
#pragma unroll
    for (int kk = 0; kk < 2; ++kk)
        offA[kk] = SOFF(w * 16 + ((lg & 1) << 3) + lr, 2 * kk + (lg >> 1));
#pragma unroll
    for (int g = 0; g < 8; ++g)
#pragma unroll
        for (int kk = 0; kk < 2; ++kk)
            offB[g][kk] = SOFF(g * 16 + ((lg >> 1) << 3) + lr, 2 * kk + (lg & 1));

    for (int s = 0; s < 8; ++s) {
        cpa_wait1();
        __syncthreads();
        const uint32_t xb = xs0 + (uint32_t)(s & 1) * BUF;
        const uint32_t wb = ws0 + (uint32_t)(s & 1) * BUF;
#pragma unroll
        for (int kk = 0; kk < 2; ++kk) {
            uint32_t af[4];
            ldsm4(af, xb + offA[kk]);
#pragma unroll
            for (int g = 0; g < 8; ++g) {
                uint32_t bf[4];
                ldsm4(bf, wb + offB[g][kk]);
                mma_f16(Cf[2 * g],     af[0], af[1], af[2], af[3], bf[0], bf[1]);
                mma_f16(Cf[2 * g + 1], af[0], af[1], af[2], af[3], bf[2], bf[3]);
            }
        }
        __syncthreads();
        if (s + 2 < 8) {
            int k0 = (s + 2) * 32;
#pragma unroll
            for (int r = 0; r < 2; ++r) {
                int id = tid + r * 256;
                int row = id >> 2, c = id & 3;
                cpa16(xb + SOFF(row, c), &g_xh[(size_t)(m0 + row) * KIN + k0 + c * 8]);
                cpa16(wb + SOFF(row, c), &wht[(size_t)row * KIN + k0 + c * 8]);
            }
        }
        cpa_commit();
    }

    const int mr0 = m0 + w * 16 + mg;
    const int mr1 = mr0 + 8;
#pragma unroll
    for (int g = 0; g < 8; ++g)
#pragma unroll
        for (int s2 = 0; s2 < 2; ++s2) {
            int n = g * 16 + s2 * 8 + 2 * mt;
            float b0 = bias[n] * bscale, b1 = bias[n + 1] * bscale;
            float* d = Cf[2 * g + s2];
            *(__half2*)&C[(size_t)mr0 * DM + n] = __floats2half2_rn(d[0] + b0, d[1] + b1);
            *(__half2*)&C[(size_t)mr1 * DM + n] = __floats2half2_rn(d[2] + b0, d[3] + b1);
        }
}

// ---------------------------------------------------------------------------
// Fused attention: fp16 mma.sync flash attention (no-max softmax, split-K),
// distance-truncated at DCUT. BM=64 (4 warps), V loads kc=0,1 hoisted.
// ---------------------------------------------------------------------------
__global__ __launch_bounds__(128, 4) void attn_kernel(const float* __restrict__ dist_w)
{
    __shared__ __align__(16) __half Qs[BM * HD];
    __shared__ __align__(16) __half Ks[2][BNO * HD];
    __shared__ __align__(16) __half Vs[2][BNO * HD];

    const int tid   = threadIdx.x;
    const int lane  = tid & 31;
    const int w     = tid >> 5;
    const int h     = blockIdx.y;
    const int sl    = blockIdx.z;
    const int qbase = blockIdx.x * BM;
    const int jbase = sl * SLICE_KEYS;

    const int mg = lane >> 2, mt = lane & 3;
    const int lg = lane >> 3, lr = lane & 7;

    const uint32_t qs0 = (uint32_t)__cvta_generic_to_shared(Qs);
    const uint32_t ks0 = (uint32_t)__cvta_generic_to_shared(Ks);
    const uint32_t vs0 = (uint32_t)__cvta_generic_to_shared(Vs);
    const uint32_t KVB = BNO * HD * 2;          // 8192 bytes per K/V buffer

    const float dwv = dist_w[h];
    const float nC2 = -dwv * 1.44269504088896340f;

    // ---- truncation window at 128-key tile granularity
    int t_lo = NKT2, t_hi = -1;
#pragma unroll
    for (int t = 0; t < NKT2; ++t) {
        int jb = jbase + t * BNO;
        int d1 = jb - (qbase + BM - 1);
        int d2 = qbase - (jb + BNO - 1);
        int mind = d1 > d2 ? d1 : d2;
        if (mind < 0) mind = 0;
        if ((float)mind * dwv <= DCUT) { if (t < t_lo) t_lo = t; t_hi = t; }
    }

    float O[4][4];
#pragma unroll
    for (int n = 0; n < 4; ++n)
#pragma unroll
        for (int r = 0; r < 4; ++r) O[n][r] = 0.f;
    float lC[4] = {0.f, 0.f, 0.f, 0.f};

    if (t_lo <= t_hi) {
        const uint32_t ONE2 = 0x3C003C00u;

        uint32_t offK[4][2], offV[4][2], offQ[2];
#pragma unroll
        for (int p = 0; p < 4; ++p)
#pragma unroll
            for (int kk = 0; kk < 2; ++kk) {
                int rowk = 16 * p + ((lg >> 1) << 3) + lr;
                offK[p][kk] = SOFF(rowk, 2 * kk + (lg & 1));
                int rowv = 16 * p + ((lg & 1) << 3) + lr;
                offV[p][kk] = SOFF(rowv, 2 * kk + (lg >> 1));
            }
#pragma unroll
        for (int kk = 0; kk < 2; ++kk) {
            int rowq = w * 16 + ((lg & 1) << 3) + lr;
            offQ[kk] = SOFF(rowq, 2 * kk + (lg >> 1));
        }

        // prologue: Q + tiles t_lo, tp1
        const int tp1 = (t_lo + 1 <= t_hi) ? (t_lo + 1) : t_lo;
        {
#pragma unroll
            for (int i = 0; i < 2; ++i) {
                int idx = tid + i * 128, r = idx >> 2, c = idx & 3;
                cpa16(qs0 + SOFF(r, c), &g_qh[(size_t)(qbase + r) * DM + h * HD + c * 8]);
            }
            {
                const int jb = jbase + t_lo * BNO;
                const uint32_t kb = ks0 + (uint32_t)(t_lo & 1) * KVB;
                const uint32_t vb = vs0 + (uint32_t)(t_lo & 1) * KVB;
#pragma unroll
                for (int i = 0; i < 4; ++i) {
                    int idx = tid + i * 128, r = idx >> 2, c = idx & 3;
                    cpa16(kb + SOFF(r, c), &g_kh[(size_t)(jb + r) * DM + h * HD + c * 8]);
                    cpa16(vb + SOFF(r, c), &g_vh[(size_t)(jb + r) * DM + h * HD + c * 8]);
                }
                cpa_commit();
            }
            {
                const int jb = jbase + tp1 * BNO;
                const uint32_t kb = ks0 + (uint32_t)((t_lo + 1) & 1) * KVB;
                const uint32_t vb = vs0 + (uint32_t)((t_lo + 1) & 1) * KVB;
#pragma unroll
                for (int i = 0; i < 4; ++i) {
                    int idx = tid + i * 128, r = idx >> 2, c = idx & 3;
                    cpa16(kb + SOFF(r, c), &g_kh[(size_t)(jb + r) * DM + h * HD + c * 8]);
                    cpa16(vb + SOFF(r, c), &g_vh[(size_t)(jb + r) * DM + h * HD + c * 8]);
                }
                cpa_commit();
            }
        }
        cpa_wait1();
        __syncthreads();

        uint32_t qf[2][4];
#pragma unroll
        for (int kk = 0; kk < 2; ++kk) ldsm4(qf[kk], qs0 + offQ[kk]);

        const float ai0   = (float)(qbase + w * 16 + mg) * 0.01f;
        const float dbase = ai0 - (float)(jbase + 2 * mt) * 0.01f;

        for (int t = t_lo; t <= t_hi; ++t) {
            const uint32_t kbB = ks0 + (uint32_t)(t & 1) * KVB;
            const uint32_t vbB = vs0 + (uint32_t)(t & 1) * KVB;

#pragma unroll
            for (int hh = 0; hh < 2; ++hh) {
                // per-64-key-half clip at window boundaries (block-uniform)
                {
                    int jbh = jbase + t * BNO + hh * 64;
                    int d1 = jbh - (qbase + BM - 1);
                    int d2 = qbase - (jbh + 63);
                    int mind = d1 > d2 ? d1 : d2;
                    if (mind > 0 && (float)mind * dwv > DCUT) continue;
                }
                const uint32_t kb = kbB + (uint32_t)hh * 4096;
                const uint32_t vb = vbB + (uint32_t)hh * 4096;

                // ---- S = Q @ K^T
                float S[8][4];
#pragma unroll
                for (int c = 0; c < 8; ++c)
#pragma unroll
                    for (int r = 0; r < 4; ++r) S[c][r] = 0.f;

                uint32_t kf[4][2][4];
#pragma unroll
                for (int p = 0; p < 4; ++p)
#pragma unroll
                    for (int kk = 0; kk < 2; ++kk) ldsm4(kf[p][kk], kb + offK[p][kk]);
#pragma unroll
                for (int p = 0; p < 4; ++p)
#pragma unroll
                    for (int s2 = 0; s2 < 2; ++s2)
#pragma unroll
                        for (int kk = 0; kk < 2; ++kk)
                            mma_f16(S[2 * p + s2], qf[kk][0], qf[kk][1], qf[kk][2], qf[kk][3],
                                    kf[p][kk][2 * s2], kf[p][kk][2 * s2 + 1]);

                // ---- hoisted V loads (kc=0,1): LDSM latency overlaps softmax
                uint32_t vf[4][2][4];
#pragma unroll
                for (int kc = 0; kc < 2; ++kc)
#pragma unroll
                    for (int dp = 0; dp < 2; ++dp) ldsm4t(vf[kc][dp], vb + offV[kc][dp]);

                // ---- p = ex2(S + nC2*|ai-aj|) via ex2.approx.f16x2
                uint32_t pp[8][2];
                const float dt = dbase - (float)t * 1.28f - (float)hh * 0.64f;
#pragma unroll
                for (int c = 0; c < 8; ++c) {
                    float d00 = dt - 0.08f * (float)c;
                    float d01 = d00 - 0.01f;
                    float d10 = d00 + 0.08f;
                    float d11 = d00 + 0.07f;
                    float a00 = fmaf(nC2, fabsf(d00), S[c][0]);
                    float a01 = fmaf(nC2, fabsf(d01), S[c][1]);
                    float a10 = fmaf(nC2, fabsf(d10), S[c][2]);
                    float a11 = fmaf(nC2, fabsf(d11), S[c][3]);
                    pp[c][0] = ex2_h2(pack_f16x2(a00, a01));
                    pp[c][1] = ex2_h2(pack_f16x2(a10, a11));
                }

                // ---- l += P @ ones
#pragma unroll
                for (int kc = 0; kc < 4; ++kc)
                    mma_f16(lC, pp[2 * kc][0], pp[2 * kc][1], pp[2 * kc + 1][0], pp[2 * kc + 1][1],
                            ONE2, ONE2);

                // ---- remaining V loads (kc=2,3), then O += P @ V
#pragma unroll
                for (int kc = 2; kc < 4; ++kc)
#pragma unroll
                    for (int dp = 0; dp < 2; ++dp) ldsm4t(vf[kc][dp], vb + offV[kc][dp]);
#pragma unroll
                for (int kc = 0; kc < 4; ++kc)
#pragma unroll
                    for (int nt = 0; nt < 4; ++nt)
                        mma_f16(O[nt], pp[2 * kc][0], pp[2 * kc][1], pp[2 * kc + 1][0], pp[2 * kc + 1][1],
                                vf[kc][nt >> 1][2 * (nt & 1)], vf[kc][nt >> 1][2 * (nt & 1) + 1]);
            }

            __syncthreads();   // all warps done with buffer (t&1)

            // ---- prefetch tile t+2 into buffer (t&1)
            if (t + 2 <= t_hi) {
                const int jb2 = jbase + (t + 2) * BNO;
                const uint32_t kb2 = ks0 + (uint32_t)(t & 1) * KVB;
                const uint32_t vb2 = vs0 + (uint32_t)(t & 1) * KVB;
#pragma unroll
                for (int i = 0; i < 4; ++i) {
                    int idx = tid + i * 128, r = idx >> 2, c = idx & 3;
                    cpa16(kb2 + SOFF(r, c), &g_kh[(size_t)(jb2 + r) * DM + h * HD + c * 8]);
                    cpa16(vb2 + SOFF(r, c), &g_vh[(size_t)(jb2 + r) * DM + h * HD + c * 8]);
                }
            }
            cpa_commit();
            if (t < t_hi) {
                cpa_wait1();
                __syncthreads();
            }
        }
    }

    // ---- epilogue: write fp16 partials (zeros if window empty)
    const int i0 = qbase + w * 16 + mg;
    const int i1 = i0 + 8;
    if (mt == 0) {
        g_lp[sl][i0 * NH + h] = lC[0];
        g_lp[sl][i1 * NH + h] = lC[2];
    }
    __half* oB = &g_attp[sl][0];
#pragma unroll
    for (int nt = 0; nt < 4; ++nt) {
        int d = nt * 8 + 2 * mt;
        *(__half2*)&oB[(size_t)i0 * DM + h * HD + d] = __floats2half2_rn(O[nt][0], O[nt][1]);
        *(__half2*)&oB[(size_t)i1 * DM + h * HD + d] = __floats2half2_rn(O[nt][2], O[nt][3]);
    }
}

// ---------------------------------------------------------------------------
// Output projection with FUSED combine (fp16 mma.sync):
// A[m][k] = fp16((sum_s attp[s][m][k]) / (sum_s l[s][m][k/32])), built into
// swizzled smem per k-stage (head index = stage), then out = A @ Wo + bo.
// ---------------------------------------------------------------------------
__global__ __launch_bounds__(128, 4) void gemm_out_tc(
    const float* __restrict__ bo, float* __restrict__ out)
{
    __shared__ __align__(16) __half As[2][64 * 32];
    __shared__ __align__(16) __half Bs[2][128 * 32];

    const int tid = threadIdx.x, lane = tid & 31, w = tid >> 5;
    const int m0 = blockIdx.x * 64;

    const int lg = lane >> 3, lr = lane & 7;
    const int mg = lane >> 2, mt = lane & 3;

    const uint32_t bs0 = (uint32_t)__cvta_generic_to_shared(Bs);
    const uint32_t BBUF = 128 * 32 * 2;

    // fill A tile for k-stage st into buffer b (combine + normalize + STS)
    auto fillA = [&](int st, int b) {
        const int k0 = st * 32;
        const int hh = st;                      // head = k0/32 (stage-constant)
#pragma unroll
        for (int i = 0; i < 2; ++i) {
            int idx = tid + i * 128;            // 0..255 (16B chunks)
            int r = idx >> 2, c = idx & 3;
            int m = m0 + r;
            float acc[8] = {0.f, 0.f, 0.f, 0.f, 0.f, 0.f, 0.f, 0.f};
            float lsum = 0.f;
#pragma unroll
            for (int s2 = 0; s2 < NSLICE; ++s2) {
                uint4 tv = *(const uint4*)&g_attp[s2][(size_t)m * DM + k0 + c * 8];
                float2 f0 = __half22float2(*(__half2*)&tv.x);
                float2 f1 = __half22float2(*(__half2*)&tv.y);
                float2 f2 = __half22float2(*(__half2*)&tv.z);
                float2 f3 = __half22float2(*(__half2*)&tv.w);
                acc[0] += f0.x; acc[1] += f0.y; acc[2] += f1.x; acc[3] += f1.y;
                acc[4] += f2.x; acc[5] += f2.y; acc[6] += f3.x; acc[7] += f3.y;
                lsum += g_lp[s2][m * NH + hh];
            }
            float inv = 1.0f / lsum;
            __half2 h0 = __floats2half2_rn(acc[0] * inv, acc[1] * inv);
            __half2 h1 = __floats2half2_rn(acc[2] * inv, acc[3] * inv);
            __half2 h2 = __floats2half2_rn(acc[4] * inv, acc[5] * inv);
            __half2 h3 = __floats2half2_rn(acc[6] * inv, acc[7] * inv);
            uint4 pk = make_uint4(*(uint32_t*)&h0, *(uint32_t*)&h1,
                                  *(uint32_t*)&h2, *(uint32_t*)&h3);
            *(uint4*)((char*)As + (size_t)b * (64 * 32 * 2) + SOFF(r, c)) = pk;
        }
    };

    // prologue: A stages 0,1 via fused combine; B stages 0,1 via cp.async
    fillA(0, 0);
    fillA(1, 1);
#pragma unroll
    for (int s = 0; s < 2; ++s) {
#pragma unroll
        for (int r = 0; r < 4; ++r) {
            int id = tid + r * 128;
            int row = id >> 2, c = id & 3;
            cpa16(bs0 + s * BBUF + SOFF(row, c), &g_woht[(size_t)row * DM + s * 32 + c * 8]);
        }
        cpa_commit();
    }

    float Cf[16][4];
#pragma unroll
    for (int f = 0; f < 16; ++f)
#pragma unroll
        for (int r = 0; r < 4; ++r) Cf[f][r] = 0.f;

    uint32_t offA[2], offB[8][2];
#pragma unroll
    for (int kk = 0; kk < 2; ++kk)
        offA[kk] = SOFF(w * 16 + ((lg & 1) << 3) + lr, 2 * kk + (lg >> 1));
#pragma unroll
    for (int g = 0; g < 8; ++g)
#pragma unroll
        for (int kk = 0; kk < 2; ++kk)
            offB[g][kk] = SOFF(g * 16 + ((lg >> 1) << 3) + lr, 2 * kk + (lg & 1));

    const uint32_t as0 = (uint32_t)__cvta_generic_to_shared(As);
    const uint32_t ABUF = 64 * 32 * 2;

    for (int s = 0; s < 4; ++s) {
        cpa_wait1();
        __syncthreads();          // B arrival + A STS visibility
        const uint32_t ab = as0 + (uint32_t)(s & 1) * ABUF;
        const uint32_t bb = bs0 + (uint32_t)(s & 1) * BBUF;
#pragma unroll
        for (int kk = 0; kk < 2; ++kk) {
            uint32_t af[4];
            ldsm4(af, ab + offA[kk]);
#pragma unroll
            for (int g = 0; g < 8; ++g) {
                uint32_t bf[4];
                ldsm4(bf, bb + offB[g][kk]);
                mma_f16(Cf[2 * g],     af[0], af[1], af[2], af[3], bf[0], bf[1]);
                mma_f16(Cf[2 * g + 1], af[0], af[1], af[2], af[3], bf[2], bf[3]);
            }
        }
        __syncthreads();          // buffer (s&1) fully consumed
        if (s + 2 < 4) {
            fillA(s + 2, s & 1);
            int k0 = (s + 2) * 32;
#pragma unroll
            for (int r = 0; r < 4; ++r) {
                int id = tid + r * 128;
                int row = id >> 2, c = id & 3;
                cpa16(bb + SOFF(row, c), &g_woht[(size_t)row * DM + k0 + c * 8]);
            }
        }
        cpa_commit();
    }

    const int mr0 = m0 + w * 16 + mg;
    const int mr1 = mr0 + 8;
#pragma unroll
    for (int g = 0; g < 8; ++g)
#pragma unroll
        for (int s2 = 0; s2 < 2; ++s2) {
            int n = g * 16 + s2 * 8 + 2 * mt;
            float b0 = bo[n], b1 = bo[n + 1];
            float* d = Cf[2 * g + s2];
            *(float2*)&out[(size_t)mr0 * DM + n] = make_float2(d[0] + b0, d[1] + b1);
            *(float2*)&out[(size_t)mr1 * DM + n] = make_float2(d[2] + b0, d[3] + b1);
        }
}

// ---------------------------------------------------------------------------
extern "C" void kernel_launch(void* const* d_in, const int* in_sizes, int n_in,
                              void* d_out, int out_size)
{
    const float* x  = (const float*)d_in[0];
    const float* Wq = (const float*)d_in[1];
    const float* bq = (const float*)d_in[2];
    const float* Wk = (const float*)d_in[3];
    const float* bk = (const float*)d_in[4];
    const float* Wv = (const float*)d_in[5];
    const float* bv = (const float*)d_in[6];
    const float* Wo = (const float*)d_in[7];
    const float* bo = (const float*)d_in[8];
    const float* dw = (const float*)d_in[9];
    float* out = (float*)d_out;

    convert_kernel<<<1600, 256>>>(x, Wq, Wk, Wv, Wo);
    gemm_qkv_tc<<<dim3(NT / 128, 3, 1), 256>>>(bq, bk, bv);
    attn_kernel<<<dim3(NT / BM, NH, NSLICE), 128>>>(dw);
    gemm_out_tc<<<NT / 64, 128>>>(bo, out);
}

// round 15
// speedup vs baseline: 1.0222x; 1.0222x over previous
#include <cuda_runtime.h>
#include <cuda_fp16.h>
#include <cstdint>

#define NT 6144
#define KIN 256
#define DM 128
#define NH 4
#define HD 32
#define NSLICE 3
#define SLICE_KEYS (NT / NSLICE)   // 2048
#define BM 64
#define BNO 128                    // outer key tile (2 inner halves of 64)
#define NKT2 (SLICE_KEYS / BNO)    // 16 outer tiles

#define C1F 0.25502050681732154f   // (1/sqrt(32)) * log2(e)
#define DCUT 1310.0f               // dist*dw cutoff: tail bias >= 13.1 => rel pert <= 1.4e-4

// Scratch (device globals: allocation-free rule)
__device__ __half g_xh[NT * KIN];
__device__ __half g_wht[3 * KIN * DM];      // transposed [w][n][k], Wq pre-scaled by C1F
__device__ __half g_woht[DM * DM];          // Wo transposed [n][k]
__device__ __half g_qh[NT * DM];
__device__ __half g_kh[NT * DM];
__device__ __half g_vh[NT * DM];
__device__ __half g_attp[NSLICE][NT * DM];  // per-slice partial sum(p*v), fp16
__device__ float g_lp[NSLICE][NT * NH];     // per-slice partial sum(p)

// ---------------------------------------------------------------------------
// PTX helpers
// ---------------------------------------------------------------------------
__device__ __forceinline__ uint32_t pack_f16x2(float lo, float hi) {
    uint32_t r; asm("cvt.rn.f16x2.f32 %0, %1, %2;" : "=r"(r) : "f"(hi), "f"(lo)); return r;
}
__device__ __forceinline__ uint32_t ex2_h2(uint32_t a) {
    uint32_t r; asm("ex2.approx.f16x2 %0, %1;" : "=r"(r) : "r"(a)); return r;
}
__device__ __forceinline__ void mma_f16(float d[4], uint32_t a0, uint32_t a1, uint32_t a2, uint32_t a3,
                                        uint32_t b0, uint32_t b1) {
    asm volatile(
        "mma.sync.aligned.m16n8k16.row.col.f32.f16.f16.f32 "
        "{%0,%1,%2,%3}, {%4,%5,%6,%7}, {%8,%9}, {%0,%1,%2,%3};\n"
        : "+f"(d[0]), "+f"(d[1]), "+f"(d[2]), "+f"(d[3])
        : "r"(a0), "r"(a1), "r"(a2), "r"(a3), "r"(b0), "r"(b1));
}
__device__ __forceinline__ void ldsm4(uint32_t r[4], uint32_t addr) {
    asm volatile("ldmatrix.sync.aligned.m8n8.x4.shared.b16 {%0,%1,%2,%3}, [%4];\n"
                 : "=r"(r[0]), "=r"(r[1]), "=r"(r[2]), "=r"(r[3]) : "r"(addr));
}
__device__ __forceinline__ void ldsm4t(uint32_t r[4], uint32_t addr) {
    asm volatile("ldmatrix.sync.aligned.m8n8.x4.trans.shared.b16 {%0,%1,%2,%3}, [%4];\n"
                 : "=r"(r[0]), "=r"(r[1]), "=r"(r[2]), "=r"(r[3]) : "r"(addr));
}
__device__ __forceinline__ void cpa16(uint32_t saddr, const void* gaddr) {
    asm volatile("cp.async.cg.shared.global [%0], [%1], 16;\n" :: "r"(saddr), "l"(gaddr));
}
__device__ __forceinline__ void cpa_commit() { asm volatile("cp.async.commit_group;\n" ::); }
__device__ __forceinline__ void cpa_wait1()  { asm volatile("cp.async.wait_group 1;\n" ::); }

// swizzled byte offset of 16B chunk (row, c) within a [rows][32 half] tile
#define SOFF(r, c) ((uint32_t)((((r) << 2) + ((c) ^ (((r) >> 1) & 3))) << 4))

// ---------------------------------------------------------------------------
// Conversion kernel: x -> fp16; Wq/Wk/Wv -> fp16 transposed (Wq scaled by C1F);
// Wo -> fp16 transposed.
// ---------------------------------------------------------------------------
__global__ __launch_bounds__(256) void convert_kernel(
    const float* __restrict__ x,
    const float* __restrict__ Wq, const float* __restrict__ Wk, const float* __restrict__ Wv,
    const float* __restrict__ Wo)
{
    const int b = blockIdx.x, tid = threadIdx.x;
    if (b < 1536) {
        int base = b * 1024 + tid * 4;
        float4 v = *(const float4*)&x[base];
        *(__half2*)&g_xh[base]     = __floats2half2_rn(v.x, v.y);
        *(__half2*)&g_xh[base + 2] = __floats2half2_rn(v.z, v.w);
    } else if (b < 1584) {
        int bb = b - 1536;              // 0..47
        int w = bb >> 4, part = bb & 15;
        const float* W = (w == 0) ? Wq : (w == 1) ? Wk : Wv;
        float scale = (w == 0) ? C1F : 1.0f;
        __half* dst = g_wht + (size_t)w * (KIN * DM);
#pragma unroll
        for (int i = tid; i < 16 * DM; i += 256) {
            int k = part * 16 + (i >> 7);
            int n = i & 127;
            dst[n * KIN + k] = __float2half(W[k * DM + n] * scale);
        }
    } else {
        int bb = b - 1584;              // 0..15
#pragma unroll
        for (int i = tid; i < 8 * DM; i += 256) {
            int k = bb * 8 + (i >> 7);
            int n = i & 127;
            g_woht[n * DM + k] = __float2half(Wo[k * DM + n]);
        }
    }
}

// ---------------------------------------------------------------------------
// QKV projection GEMM (fp16 mma.sync): C = x @ W + b, output fp16.
// ---------------------------------------------------------------------------
__global__ __launch_bounds__(256, 2) void gemm_qkv_tc(
    const float* __restrict__ bq, const float* __restrict__ bk, const float* __restrict__ bv)
{
    __shared__ __align__(16) __half Xs[2][128 * 32];
    __shared__ __align__(16) __half Ws[2][128 * 32];

    const int tid = threadIdx.x, lane = tid & 31, w = tid >> 5;
    const int y = blockIdx.y;
    const int m0 = blockIdx.x * 128;
    const __half* wht = g_wht + (size_t)y * (KIN * DM);
    const float* bias = (y == 0) ? bq : (y == 1) ? bk : bv;
    const float bscale = (y == 0) ? C1F : 1.0f;
    __half* C = (y == 0) ? g_qh : (y == 1) ? g_kh : g_vh;

    const int lg = lane >> 3, lr = lane & 7;
    const int mg = lane >> 2, mt = lane & 3;

    const uint32_t xs0 = (uint32_t)__cvta_generic_to_shared(Xs);
    const uint32_t ws0 = (uint32_t)__cvta_generic_to_shared(Ws);
    const uint32_t BUF = 128 * 32 * 2;

#pragma unroll
    for (int s = 0; s < 2; ++s) {
#pragma unroll
        for (int r = 0; r < 2; ++r) {
            int id = tid + r * 256;
            int row = id >> 2, c = id & 3;
            cpa16(xs0 + s * BUF + SOFF(row, c), &g_xh[(size_t)(m0 + row) * KIN + s * 32 + c * 8]);
            cpa16(ws0 + s * BUF + SOFF(row, c), &wht[(size_t)row * KIN + s * 32 + c * 8]);
        }
        cpa_commit();
    }

    float Cf[16][4];
#pragma unroll
    for (int f = 0; f < 16; ++f)
#pragma unroll
        for (int r = 0; r < 4; ++r) Cf[f][r] = 0.f;

    uint32_t offA[2], offB[8][2];
#pragma unroll
    for (int kk = 0; kk < 2; ++kk)
        offA[kk] = SOFF(w * 16 + ((lg & 1) << 3) + lr, 2 * kk + (lg >> 1));
#pragma unroll
    for (int g = 0; g < 8; ++g)
#pragma unroll
        for (int kk = 0; kk < 2; ++kk)
            offB[g][kk] = SOFF(g * 16 + ((lg >> 1) << 3) + lr, 2 * kk + (lg & 1));

    for (int s = 0; s < 8; ++s) {
        cpa_wait1();
        __syncthreads();
        const uint32_t xb = xs0 + (uint32_t)(s & 1) * BUF;
        const uint32_t wb = ws0 + (uint32_t)(s & 1) * BUF;
#pragma unroll
        for (int kk = 0; kk < 2; ++kk) {
            uint32_t af[4];
            ldsm4(af, xb + offA[kk]);
#pragma unroll
            for (int g = 0; g < 8; ++g) {
                uint32_t bf[4];
                ldsm4(bf, wb + offB[g][kk]);
                mma_f16(Cf[2 * g],     af[0], af[1], af[2], af[3], bf[0], bf[1]);
                mma_f16(Cf[2 * g + 1], af[0], af[1], af[2], af[3], bf[2], bf[3]);
            }
        }
        __syncthreads();
        if (s + 2 < 8) {
            int k0 = (s + 2) * 32;
#pragma unroll
            for (int r = 0; r < 2; ++r) {
                int id = tid + r * 256;
                int row = id >> 2, c = id & 3;
                cpa16(xb + SOFF(row, c), &g_xh[(size_t)(m0 + row) * KIN + k0 + c * 8]);
                cpa16(wb + SOFF(row, c), &wht[(size_t)row * KIN + k0 + c * 8]);
            }
        }
        cpa_commit();
    }

    const int mr0 = m0 + w * 16 + mg;
    const int mr1 = mr0 + 8;
#pragma unroll
    for (int g = 0; g < 8; ++g)
#pragma unroll
        for (int s2 = 0; s2 < 2; ++s2) {
            int n = g * 16 + s2 * 8 + 2 * mt;
            float b0 = bias[n] * bscale, b1 = bias[n + 1] * bscale;
            float* d = Cf[2 * g + s2];
            *(__half2*)&C[(size_t)mr0 * DM + n] = __floats2half2_rn(d[0] + b0, d[1] + b1);
            *(__half2*)&C[(size_t)mr1 * DM + n] = __floats2half2_rn(d[2] + b0, d[3] + b1);
        }
}

// ---------------------------------------------------------------------------
// Fused attention: fp16 mma.sync flash attention (no-max softmax, split-K),
// distance-truncated at DCUT. BM=64 (4 warps), V loads kc=0,1 hoisted.
// ---------------------------------------------------------------------------
__global__ __launch_bounds__(128, 4) void attn_kernel(const float* __restrict__ dist_w)
{
    __shared__ __align__(16) __half Qs[BM * HD];
    __shared__ __align__(16) __half Ks[2][BNO * HD];
    __shared__ __align__(16) __half Vs[2][BNO * HD];

    const int tid   = threadIdx.x;
    const int lane  = tid & 31;
    const int w     = tid >> 5;
    const int h     = blockIdx.y;
    const int sl    = blockIdx.z;
    const int qbase = blockIdx.x * BM;
    const int jbase = sl * SLICE_KEYS;

    const int mg = lane >> 2, mt = lane & 3;
    const int lg = lane >> 3, lr = lane & 7;

    const uint32_t qs0 = (uint32_t)__cvta_generic_to_shared(Qs);
    const uint32_t ks0 = (uint32_t)__cvta_generic_to_shared(Ks);
    const uint32_t vs0 = (uint32_t)__cvta_generic_to_shared(Vs);
    const uint32_t KVB = BNO * HD * 2;          // 8192 bytes per K/V buffer

    const float dwv = dist_w[h];
    const float nC2 = -dwv * 1.44269504088896340f;

    // ---- truncation window at 128-key tile granularity
    int t_lo = NKT2, t_hi = -1;
#pragma unroll
    for (int t = 0; t < NKT2; ++t) {
        int jb = jbase + t * BNO;
        int d1 = jb - (qbase + BM - 1);
        int d2 = qbase - (jb + BNO - 1);
        int mind = d1 > d2 ? d1 : d2;
        if (mind < 0) mind = 0;
        if ((float)mind * dwv <= DCUT) { if (t < t_lo) t_lo = t; t_hi = t; }
    }

    float O[4][4];
#pragma unroll
    for (int n = 0; n < 4; ++n)
#pragma unroll
        for (int r = 0; r < 4; ++r) O[n][r] = 0.f;
    float lC[4] = {0.f, 0.f, 0.f, 0.f};

    if (t_lo <= t_hi) {
        const uint32_t ONE2 = 0x3C003C00u;

        uint32_t offK[4][2], offV[4][2], offQ[2];
#pragma unroll
        for (int p = 0; p < 4; ++p)
#pragma unroll
            for (int kk = 0; kk < 2; ++kk) {
                int rowk = 16 * p + ((lg >> 1) << 3) + lr;
                offK[p][kk] = SOFF(rowk, 2 * kk + (lg & 1));
                int rowv = 16 * p + ((lg & 1) << 3) + lr;
                offV[p][kk] = SOFF(rowv, 2 * kk + (lg >> 1));
            }
#pragma unroll
        for (int kk = 0; kk < 2; ++kk) {
            int rowq = w * 16 + ((lg & 1) << 3) + lr;
            offQ[kk] = SOFF(rowq, 2 * kk + (lg >> 1));
        }

        // prologue: Q + tiles t_lo, tp1
        const int tp1 = (t_lo + 1 <= t_hi) ? (t_lo + 1) : t_lo;
        {
#pragma unroll
            for (int i = 0; i < 2; ++i) {
                int idx = tid + i * 128, r = idx >> 2, c = idx & 3;
                cpa16(qs0 + SOFF(r, c), &g_qh[(size_t)(qbase + r) * DM + h * HD + c * 8]);
            }
            {
                const int jb = jbase + t_lo * BNO;
                const uint32_t kb = ks0 + (uint32_t)(t_lo & 1) * KVB;
                const uint32_t vb = vs0 + (uint32_t)(t_lo & 1) * KVB;
#pragma unroll
                for (int i = 0; i < 4; ++i) {
                    int idx = tid + i * 128, r = idx >> 2, c = idx & 3;
                    cpa16(kb + SOFF(r, c), &g_kh[(size_t)(jb + r) * DM + h * HD + c * 8]);
                    cpa16(vb + SOFF(r, c), &g_vh[(size_t)(jb + r) * DM + h * HD + c * 8]);
                }
                cpa_commit();
            }
            {
                const int jb = jbase + tp1 * BNO;
                const uint32_t kb = ks0 + (uint32_t)((t_lo + 1) & 1) * KVB;
                const uint32_t vb = vs0 + (uint32_t)((t_lo + 1) & 1) * KVB;
#pragma unroll
                for (int i = 0; i < 4; ++i) {
                    int idx = tid + i * 128, r = idx >> 2, c = idx & 3;
                    cpa16(kb + SOFF(r, c), &g_kh[(size_t)(jb + r) * DM + h * HD + c * 8]);
                    cpa16(vb + SOFF(r, c), &g_vh[(size_t)(jb + r) * DM + h * HD + c * 8]);
                }
                cpa_commit();
            }
        }
        cpa_wait1();
        __syncthreads();

        uint32_t qf[2][4];
#pragma unroll
        for (int kk = 0; kk < 2; ++kk) ldsm4(qf[kk], qs0 + offQ[kk]);

        const float ai0   = (float)(qbase + w * 16 + mg) * 0.01f;
        const float dbase = ai0 - (float)(jbase + 2 * mt) * 0.01f;

        for (int t = t_lo; t <= t_hi; ++t) {
            const uint32_t kbB = ks0 + (uint32_t)(t & 1) * KVB;
            const uint32_t vbB = vs0 + (uint32_t)(t & 1) * KVB;

#pragma unroll
            for (int hh = 0; hh < 2; ++hh) {
                // per-64-key-half clip at window boundaries (block-uniform)
                {
                    int jbh = jbase + t * BNO + hh * 64;
                    int d1 = jbh - (qbase + BM - 1);
                    int d2 = qbase - (jbh + 63);
                    int mind = d1 > d2 ? d1 : d2;
                    if (mind > 0 && (float)mind * dwv > DCUT) continue;
                }
                const uint32_t kb = kbB + (uint32_t)hh * 4096;
                const uint32_t vb = vbB + (uint32_t)hh * 4096;

                // ---- S = Q @ K^T
                float S[8][4];
#pragma unroll
                for (int c = 0; c < 8; ++c)
#pragma unroll
                    for (int r = 0; r < 4; ++r) S[c][r] = 0.f;

                uint32_t kf[4][2][4];
#pragma unroll
                for (int p = 0; p < 4; ++p)
#pragma unroll
                    for (int kk = 0; kk < 2; ++kk) ldsm4(kf[p][kk], kb + offK[p][kk]);
#pragma unroll
                for (int p = 0; p < 4; ++p)
#pragma unroll
                    for (int s2 = 0; s2 < 2; ++s2)
#pragma unroll
                        for (int kk = 0; kk < 2; ++kk)
                            mma_f16(S[2 * p + s2], qf[kk][0], qf[kk][1], qf[kk][2], qf[kk][3],
                                    kf[p][kk][2 * s2], kf[p][kk][2 * s2 + 1]);

                // ---- hoisted V loads (kc=0,1): LDSM latency overlaps softmax
                uint32_t vf[4][2][4];
#pragma unroll
                for (int kc = 0; kc < 2; ++kc)
#pragma unroll
                    for (int dp = 0; dp < 2; ++dp) ldsm4t(vf[kc][dp], vb + offV[kc][dp]);

                // ---- p = ex2(S + nC2*|ai-aj|) via ex2.approx.f16x2
                uint32_t pp[8][2];
                const float dt = dbase - (float)t * 1.28f - (float)hh * 0.64f;
#pragma unroll
                for (int c = 0; c < 8; ++c) {
                    float d00 = dt - 0.08f * (float)c;
                    float d01 = d00 - 0.01f;
                    float d10 = d00 + 0.08f;
                    float d11 = d00 + 0.07f;
                    float a00 = fmaf(nC2, fabsf(d00), S[c][0]);
                    float a01 = fmaf(nC2, fabsf(d01), S[c][1]);
                    float a10 = fmaf(nC2, fabsf(d10), S[c][2]);
                    float a11 = fmaf(nC2, fabsf(d11), S[c][3]);
                    pp[c][0] = ex2_h2(pack_f16x2(a00, a01));
                    pp[c][1] = ex2_h2(pack_f16x2(a10, a11));
                }

                // ---- l += P @ ones
#pragma unroll
                for (int kc = 0; kc < 4; ++kc)
                    mma_f16(lC, pp[2 * kc][0], pp[2 * kc][1], pp[2 * kc + 1][0], pp[2 * kc + 1][1],
                            ONE2, ONE2);

                // ---- remaining V loads (kc=2,3), then O += P @ V
#pragma unroll
                for (int kc = 2; kc < 4; ++kc)
#pragma unroll
                    for (int dp = 0; dp < 2; ++dp) ldsm4t(vf[kc][dp], vb + offV[kc][dp]);
#pragma unroll
                for (int kc = 0; kc < 4; ++kc)
#pragma unroll
                    for (int nt = 0; nt < 4; ++nt)
                        mma_f16(O[nt], pp[2 * kc][0], pp[2 * kc][1], pp[2 * kc + 1][0], pp[2 * kc + 1][1],
                                vf[kc][nt >> 1][2 * (nt & 1)], vf[kc][nt >> 1][2 * (nt & 1) + 1]);
            }

            __syncthreads();   // all warps done with buffer (t&1)

            // ---- prefetch tile t+2 into buffer (t&1)
            if (t + 2 <= t_hi) {
                const int jb2 = jbase + (t + 2) * BNO;
                const uint32_t kb2 = ks0 + (uint32_t)(t & 1) * KVB;
                const uint32_t vb2 = vs0 + (uint32_t)(t & 1) * KVB;
#pragma unroll
                for (int i = 0; i < 4; ++i) {
                    int idx = tid + i * 128, r = idx >> 2, c = idx & 3;
                    cpa16(kb2 + SOFF(r, c), &g_kh[(size_t)(jb2 + r) * DM + h * HD + c * 8]);
                    cpa16(vb2 + SOFF(r, c), &g_vh[(size_t)(jb2 + r) * DM + h * HD + c * 8]);
                }
            }
            cpa_commit();
            if (t < t_hi) {
                cpa_wait1();
                __syncthreads();
            }
        }
    }

    // ---- epilogue: write fp16 partials (zeros if window empty)
    const int i0 = qbase + w * 16 + mg;
    const int i1 = i0 + 8;
    if (mt == 0) {
        g_lp[sl][i0 * NH + h] = lC[0];
        g_lp[sl][i1 * NH + h] = lC[2];
    }
    __half* oB = &g_attp[sl][0];
#pragma unroll
    for (int nt = 0; nt < 4; ++nt) {
        int d = nt * 8 + 2 * mt;
        *(__half2*)&oB[(size_t)i0 * DM + h * HD + d] = __floats2half2_rn(O[nt][0], O[nt][1]);
        *(__half2*)&oB[(size_t)i1 * DM + h * HD + d] = __floats2half2_rn(O[nt][2], O[nt][3]);
    }
}

// ---------------------------------------------------------------------------
// Output projection with FUSED combine (fp16 mma.sync), BM=32, grid 192.
// Warps: wm = w&1 selects 16-row group, wn = w>>1 selects 64-col N half.
// A[m][k] = fp16((sum_s attp)/(sum_s l)) built into swizzled smem per stage.
// ---------------------------------------------------------------------------
__global__ __launch_bounds__(128, 8) void gemm_out_tc(
    const float* __restrict__ bo, float* __restrict__ out)
{
    __shared__ __align__(16) __half As[2][32 * 32];
    __shared__ __align__(16) __half Bs[2][128 * 32];

    const int tid = threadIdx.x, lane = tid & 31, w = tid >> 5;
    const int wm = w & 1, wn = w >> 1;
    const int m0 = blockIdx.x * 32;

    const int lg = lane >> 3, lr = lane & 7;
    const int mg = lane >> 2, mt = lane & 3;

    const uint32_t bs0 = (uint32_t)__cvta_generic_to_shared(Bs);
    const uint32_t BBUF = 128 * 32 * 2;

    // fill A tile (32x32) for k-stage st into buffer b: 1 chunk per thread
    auto fillA = [&](int st, int b) {
        const int k0 = st * 32;
        const int hh = st;                      // head = k0/32 (stage-constant)
        int r = tid >> 2, c = tid & 3;          // 128 chunks
        int m = m0 + r;
        float acc[8] = {0.f, 0.f, 0.f, 0.f, 0.f, 0.f, 0.f, 0.f};
        float lsum = 0.f;
#pragma unroll
        for (int s2 = 0; s2 < NSLICE; ++s2) {
            uint4 tv = *(const uint4*)&g_attp[s2][(size_t)m * DM + k0 + c * 8];
            float2 f0 = __half22float2(*(__half2*)&tv.x);
            float2 f1 = __half22float2(*(__half2*)&tv.y);
            float2 f2 = __half22float2(*(__half2*)&tv.z);
            float2 f3 = __half22float2(*(__half2*)&tv.w);
            acc[0] += f0.x; acc[1] += f0.y; acc[2] += f1.x; acc[3] += f1.y;
            acc[4] += f2.x; acc[5] += f2.y; acc[6] += f3.x; acc[7] += f3.y;
            lsum += g_lp[s2][m * NH + hh];
        }
        float inv = 1.0f / lsum;
        __half2 h0 = __floats2half2_rn(acc[0] * inv, acc[1] * inv);
        __half2 h1 = __floats2half2_rn(acc[2] * inv, acc[3] * inv);
        __half2 h2 = __floats2half2_rn(acc[4] * inv, acc[5] * inv);
        __half2 h3 = __floats2half2_rn(acc[6] * inv, acc[7] * inv);
        uint4 pk = make_uint4(*(uint32_t*)&h0, *(uint32_t*)&h1,
                              *(uint32_t*)&h2, *(uint32_t*)&h3);
        *(uint4*)((char*)As + (size_t)b * (32 * 32 * 2) + SOFF(r, c)) = pk;
    };

    // prologue: A stages 0,1 (fused combine); B stages 0,1 (cp.async)
    fillA(0, 0);
    fillA(1, 1);
#pragma unroll
    for (int s = 0; s < 2; ++s) {
#pragma unroll
        for (int r = 0; r < 4; ++r) {
            int id = tid + r * 128;
            int row = id >> 2, c = id & 3;
            cpa16(bs0 + s * BBUF + SOFF(row, c), &g_woht[(size_t)row * DM + s * 32 + c * 8]);
        }
        cpa_commit();
    }

    float Cf[8][4];
#pragma unroll
    for (int f = 0; f < 8; ++f)
#pragma unroll
        for (int r = 0; r < 4; ++r) Cf[f][r] = 0.f;

    uint32_t offA[2], offB[4][2];
#pragma unroll
    for (int kk = 0; kk < 2; ++kk)
        offA[kk] = SOFF(wm * 16 + ((lg & 1) << 3) + lr, 2 * kk + (lg >> 1));
#pragma unroll
    for (int g = 0; g < 4; ++g)
#pragma unroll
        for (int kk = 0; kk < 2; ++kk)
            offB[g][kk] = SOFF(wn * 64 + g * 16 + ((lg >> 1) << 3) + lr, 2 * kk + (lg & 1));

    const uint32_t as0 = (uint32_t)__cvta_generic_to_shared(As);
    const uint32_t ABUF = 32 * 32 * 2;

    for (int s = 0; s < 4; ++s) {
        cpa_wait1();
        __syncthreads();          // B arrival + A STS visibility
        const uint32_t ab = as0 + (uint32_t)(s & 1) * ABUF;
        const uint32_t bb = bs0 + (uint32_t)(s & 1) * BBUF;
#pragma unroll
        for (int kk = 0; kk < 2; ++kk) {
            uint32_t af[4];
            ldsm4(af, ab + offA[kk]);
#pragma unroll
            for (int g = 0; g < 4; ++g) {
                uint32_t bf[4];
                ldsm4(bf, bb + offB[g][kk]);
                mma_f16(Cf[2 * g],     af[0], af[1], af[2], af[3], bf[0], bf[1]);
                mma_f16(Cf[2 * g + 1], af[0], af[1], af[2], af[3], bf[2], bf[3]);
            }
        }
        __syncthreads();          // buffer (s&1) fully consumed
        if (s + 2 < 4) {
            fillA(s + 2, s & 1);
            int k0 = (s + 2) * 32;
#pragma unroll
            for (int r = 0; r < 4; ++r) {
                int id = tid + r * 128;
                int row = id >> 2, c = id & 3;
                cpa16(bb + SOFF(row, c), &g_woht[(size_t)row * DM + k0 + c * 8]);
            }
        }
        cpa_commit();
    }

    const int mr0 = m0 + wm * 16 + mg;
    const int mr1 = mr0 + 8;
#pragma unroll
    for (int g = 0; g < 4; ++g)
#pragma unroll
        for (int s2 = 0; s2 < 2; ++s2) {
            int n = wn * 64 + g * 16 + s2 * 8 + 2 * mt;
            float b0 = bo[n], b1 = bo[n + 1];
            float* d = Cf[2 * g + s2];
            *(float2*)&out[(size_t)mr0 * DM + n] = make_float2(d[0] + b0, d[1] + b1);
            *(float2*)&out[(size_t)mr1 * DM + n] = make_float2(d[2] + b0, d[3] + b1);
        }
}

// ---------------------------------------------------------------------------
extern "C" void kernel_launch(void* const* d_in, const int* in_sizes, int n_in,
                              void* d_out, int out_size)
{
    const float* x  = (const float*)d_in[0];
    const float* Wq = (const float*)d_in[1];
    const float* bq = (const float*)d_in[2];
    const float* Wk = (const float*)d_in[3];
    const float* bk = (const float*)d_in[4];
    const float* Wv = (const float*)d_in[5];
    const float* bv = (const float*)d_in[6];
    const float* Wo = (const float*)d_in[7];
    const float* bo = (const float*)d_in[8];
    const float* dw = (const float*)d_in[9];
    float* out = (float*)d_out;

    convert_kernel<<<1600, 256>>>(x, Wq, Wk, Wv, Wo);
    gemm_qkv_tc<<<dim3(NT / 128, 3, 1), 256>>>(bq, bk, bv);
    attn_kernel<<<dim3(NT / BM, NH, NSLICE), 128>>>(dw);
    gemm_out_tc<<<NT / 32, 128>>>(bo, out);
}

// round 16
// speedup vs baseline: 1.0434x; 1.0207x over previous
#include <cuda_runtime.h>
#include <cuda_fp16.h>
#include <cstdint>

#define NT 6144
#define KIN 256
#define DM 128
#define NH 4
#define HD 32
#define NSLICE 3
#define SLICE_KEYS (NT / NSLICE)   // 2048
#define BM 64
#define BNO 128                    // outer key tile (2 inner halves of 64)
#define NKT2 (SLICE_KEYS / BNO)    // 16 outer tiles

#define C1F 0.25502050681732154f   // (1/sqrt(32)) * log2(e)
#define DCUT 1310.0f               // dist*dw cutoff: tail bias >= 13.1 => rel pert <= 1.4e-4

// Scratch (device globals: allocation-free rule)
__device__ __half g_xh[NT * KIN];
__device__ __half g_wht[3 * KIN * DM];      // transposed [w][n][k], Wq pre-scaled by C1F
__device__ __half g_woht[DM * DM];          // Wo transposed [n][k]
__device__ __half g_qh[NT * DM];
__device__ __half g_kh[NT * DM];
__device__ __half g_vh[NT * DM];
__device__ __half g_attp[NSLICE][NT * DM];  // per-slice partial sum(p*v), fp16
__device__ float g_lp[NSLICE][NT * NH];     // per-slice partial sum(p)

// ---------------------------------------------------------------------------
// PTX helpers
// ---------------------------------------------------------------------------
__device__ __forceinline__ uint32_t pack_f16x2(float lo, float hi) {
    uint32_t r; asm("cvt.rn.f16x2.f32 %0, %1, %2;" : "=r"(r) : "f"(hi), "f"(lo)); return r;
}
__device__ __forceinline__ uint32_t ex2_h2(uint32_t a) {
    uint32_t r; asm("ex2.approx.f16x2 %0, %1;" : "=r"(r) : "r"(a)); return r;
}
__device__ __forceinline__ void mma_f16(float d[4], uint32_t a0, uint32_t a1, uint32_t a2, uint32_t a3,
                                        uint32_t b0, uint32_t b1) {
    asm volatile(
        "mma.sync.aligned.m16n8k16.row.col.f32.f16.f16.f32 "
        "{%0,%1,%2,%3}, {%4,%5,%6,%7}, {%8,%9}, {%0,%1,%2,%3};\n"
        : "+f"(d[0]), "+f"(d[1]), "+f"(d[2]), "+f"(d[3])
        : "r"(a0), "r"(a1), "r"(a2), "r"(a3), "r"(b0), "r"(b1));
}
__device__ __forceinline__ void ldsm4(uint32_t r[4], uint32_t addr) {
    asm volatile("ldmatrix.sync.aligned.m8n8.x4.shared.b16 {%0,%1,%2,%3}, [%4];\n"
                 : "=r"(r[0]), "=r"(r[1]), "=r"(r[2]), "=r"(r[3]) : "r"(addr));
}
__device__ __forceinline__ void ldsm4t(uint32_t r[4], uint32_t addr) {
    asm volatile("ldmatrix.sync.aligned.m8n8.x4.trans.shared.b16 {%0,%1,%2,%3}, [%4];\n"
                 : "=r"(r[0]), "=r"(r[1]), "=r"(r[2]), "=r"(r[3]) : "r"(addr));
}
__device__ __forceinline__ void cpa16(uint32_t saddr, const void* gaddr) {
    asm volatile("cp.async.cg.shared.global [%0], [%1], 16;\n" :: "r"(saddr), "l"(gaddr));
}
__device__ __forceinline__ void cpa_commit() { asm volatile("cp.async.commit_group;\n" ::); }
__device__ __forceinline__ void cpa_wait1()  { asm volatile("cp.async.wait_group 1;\n" ::); }
__device__ __forceinline__ uint4 ldg128(const void* p) {
    uint4 v;
    asm volatile("ld.global.v4.u32 {%0,%1,%2,%3}, [%4];"
                 : "=r"(v.x), "=r"(v.y), "=r"(v.z), "=r"(v.w) : "l"(p));
    return v;
}

// swizzled byte offset of 16B chunk (row, c) within a [rows][32 half] tile
#define SOFF(r, c) ((uint32_t)((((r) << 2) + ((c) ^ (((r) >> 1) & 3))) << 4))

// ---------------------------------------------------------------------------
// Conversion kernel: x -> fp16; Wq/Wk/Wv -> fp16 transposed (Wq scaled by C1F);
// Wo -> fp16 transposed.
// ---------------------------------------------------------------------------
__global__ __launch_bounds__(256) void convert_kernel(
    const float* __restrict__ x,
    const float* __restrict__ Wq, const float* __restrict__ Wk, const float* __restrict__ Wv,
    const float* __restrict__ Wo)
{
    const int b = blockIdx.x, tid = threadIdx.x;
    if (b < 1536) {
        int base = b * 1024 + tid * 4;
        float4 v = *(const float4*)&x[base];
        *(__half2*)&g_xh[base]     = __floats2half2_rn(v.x, v.y);
        *(__half2*)&g_xh[base + 2] = __floats2half2_rn(v.z, v.w);
    } else if (b < 1584) {
        int bb = b - 1536;              // 0..47
        int w = bb >> 4, part = bb & 15;
        const float* W = (w == 0) ? Wq : (w == 1) ? Wk : Wv;
        float scale = (w == 0) ? C1F : 1.0f;
        __half* dst = g_wht + (size_t)w * (KIN * DM);
#pragma unroll
        for (int i = tid; i < 16 * DM; i += 256) {
            int k = part * 16 + (i >> 7);
            int n = i & 127;
            dst[n * KIN + k] = __float2half(W[k * DM + n] * scale);
        }
    } else {
        int bb = b - 1584;              // 0..15
#pragma unroll
        for (int i = tid; i < 8 * DM; i += 256) {
            int k = bb * 8 + (i >> 7);
            int n = i & 127;
            g_woht[n * DM + k] = __float2half(Wo[k * DM + n]);
        }
    }
}

// ---------------------------------------------------------------------------
// QKV projection GEMM (fp16 mma.sync): C = x @ W + b, output fp16.
// ---------------------------------------------------------------------------
__global__ __launch_bounds__(256, 2) void gemm_qkv_tc(
    const float* __restrict__ bq, const float* __restrict__ bk, const float* __restrict__ bv)
{
    __shared__ __align__(16) __half Xs[2][128 * 32];
    __shared__ __align__(16) __half Ws[2][128 * 32];

    const int tid = threadIdx.x, lane = tid & 31, w = tid >> 5;
    const int y = blockIdx.y;
    const int m0 = blockIdx.x * 128;
    const __half* wht = g_wht + (size_t)y * (KIN * DM);
    const float* bias = (y == 0) ? bq : (y == 1) ? bk : bv;
    const float bscale = (y == 0) ? C1F : 1.0f;
    __half* C = (y == 0) ? g_qh : (y == 1) ? g_kh : g_vh;

    const int lg = lane >> 3, lr = lane & 7;
    const int mg = lane >> 2, mt = lane & 3;

    const uint32_t xs0 = (uint32_t)__cvta_generic_to_shared(Xs);
    const uint32_t ws0 = (uint32_t)__cvta_generic_to_shared(Ws);
    const uint32_t BUF = 128 * 32 * 2;

#pragma unroll
    for (int s = 0; s < 2; ++s) {
#pragma unroll
        for (int r = 0; r < 2; ++r) {
            int id = tid + r * 256;
            int row = id >> 2, c = id & 3;
            cpa16(xs0 + s * BUF + SOFF(row, c), &g_xh[(size_t)(m0 + row) * KIN + s * 32 + c * 8]);
            cpa16(ws0 + s * BUF + SOFF(row, c), &wht[(size_t)row * KIN + s * 32 + c * 8]);
        }
        cpa_commit();
    }

    float Cf[16][4];
#pragma unroll
    for (int f = 0; f < 16; ++f)
#pragma unroll
        for (int r = 0; r < 4; ++r) Cf[f][r] = 0.f;

    uint32_t offA[2], offB[8][2];
#pragma unroll
    for (int kk = 0; kk < 2; ++kk)
        offA[kk] = SOFF(w * 16 + ((lg & 1) << 3) + lr, 2 * kk + (lg >> 1));
#pragma unroll
    for (int g = 0; g < 8; ++g)
#pragma unroll
        for (int kk = 0; kk < 2; ++kk)
            offB[g][kk] = SOFF(g * 16 + ((lg >> 1) << 3) + lr, 2 * kk + (lg & 1));

    for (int s = 0; s < 8; ++s) {
        cpa_wait1();
        __syncthreads();
        const uint32_t xb = xs0 + (uint32_t)(s & 1) * BUF;
        const uint32_t wb = ws0 + (uint32_t)(s & 1) * BUF;
#pragma unroll
        for (int kk = 0; kk < 2; ++kk) {
            uint32_t af[4];
            ldsm4(af, xb + offA[kk]);
#pragma unroll
            for (int g = 0; g < 8; ++g) {
                uint32_t bf[4];
                ldsm4(bf, wb + offB[g][kk]);
                mma_f16(Cf[2 * g],     af[0], af[1], af[2], af[3], bf[0], bf[1]);
                mma_f16(Cf[2 * g + 1], af[0], af[1], af[2], af[3], bf[2], bf[3]);
            }
        }
        __syncthreads();
        if (s + 2 < 8) {
            int k0 = (s + 2) * 32;
#pragma unroll
            for (int r = 0; r < 2; ++r) {
                int id = tid + r * 256;
                int row = id >> 2, c = id & 3;
                cpa16(xb + SOFF(row, c), &g_xh[(size_t)(m0 + row) * KIN + k0 + c * 8]);
                cpa16(wb + SOFF(row, c), &wht[(size_t)row * KIN + k0 + c * 8]);
            }
        }
        cpa_commit();
    }

    const int mr0 = m0 + w * 16 + mg;
    const int mr1 = mr0 + 8;
#pragma unroll
    for (int g = 0; g < 8; ++g)
#pragma unroll
        for (int s2 = 0; s2 < 2; ++s2) {
            int n = g * 16 + s2 * 8 + 2 * mt;
            float b0 = bias[n] * bscale, b1 = bias[n + 1] * bscale;
            float* d = Cf[2 * g + s2];
            *(__half2*)&C[(size_t)mr0 * DM + n] = __floats2half2_rn(d[0] + b0, d[1] + b1);
            *(__half2*)&C[(size_t)mr1 * DM + n] = __floats2half2_rn(d[2] + b0, d[3] + b1);
        }
}

// ---------------------------------------------------------------------------
// Fused attention: fp16 mma.sync flash attention (no-max softmax, split-K),
// distance-truncated at DCUT. BM=64 (4 warps), V loads kc=0,1 hoisted.
// ---------------------------------------------------------------------------
__global__ __launch_bounds__(128, 4) void attn_kernel(const float* __restrict__ dist_w)
{
    __shared__ __align__(16) __half Qs[BM * HD];
    __shared__ __align__(16) __half Ks[2][BNO * HD];
    __shared__ __align__(16) __half Vs[2][BNO * HD];

    const int tid   = threadIdx.x;
    const int lane  = tid & 31;
    const int w     = tid >> 5;
    const int h     = blockIdx.y;
    const int sl    = blockIdx.z;
    const int qbase = blockIdx.x * BM;
    const int jbase = sl * SLICE_KEYS;

    const int mg = lane >> 2, mt = lane & 3;
    const int lg = lane >> 3, lr = lane & 7;

    const uint32_t qs0 = (uint32_t)__cvta_generic_to_shared(Qs);
    const uint32_t ks0 = (uint32_t)__cvta_generic_to_shared(Ks);
    const uint32_t vs0 = (uint32_t)__cvta_generic_to_shared(Vs);
    const uint32_t KVB = BNO * HD * 2;          // 8192 bytes per K/V buffer

    const float dwv = dist_w[h];
    const float nC2 = -dwv * 1.44269504088896340f;

    // ---- truncation window at 128-key tile granularity
    int t_lo = NKT2, t_hi = -1;
#pragma unroll
    for (int t = 0; t < NKT2; ++t) {
        int jb = jbase + t * BNO;
        int d1 = jb - (qbase + BM - 1);
        int d2 = qbase - (jb + BNO - 1);
        int mind = d1 > d2 ? d1 : d2;
        if (mind < 0) mind = 0;
        if ((float)mind * dwv <= DCUT) { if (t < t_lo) t_lo = t; t_hi = t; }
    }

    float O[4][4];
#pragma unroll
    for (int n = 0; n < 4; ++n)
#pragma unroll
        for (int r = 0; r < 4; ++r) O[n][r] = 0.f;
    float lC[4] = {0.f, 0.f, 0.f, 0.f};

    if (t_lo <= t_hi) {
        const uint32_t ONE2 = 0x3C003C00u;

        uint32_t offK[4][2], offV[4][2], offQ[2];
#pragma unroll
        for (int p = 0; p < 4; ++p)
#pragma unroll
            for (int kk = 0; kk < 2; ++kk) {
                int rowk = 16 * p + ((lg >> 1) << 3) + lr;
                offK[p][kk] = SOFF(rowk, 2 * kk + (lg & 1));
                int rowv = 16 * p + ((lg & 1) << 3) + lr;
                offV[p][kk] = SOFF(rowv, 2 * kk + (lg >> 1));
            }
#pragma unroll
        for (int kk = 0; kk < 2; ++kk) {
            int rowq = w * 16 + ((lg & 1) << 3) + lr;
            offQ[kk] = SOFF(rowq, 2 * kk + (lg >> 1));
        }

        // prologue: Q + tiles t_lo, tp1
        const int tp1 = (t_lo + 1 <= t_hi) ? (t_lo + 1) : t_lo;
        {
#pragma unroll
            for (int i = 0; i < 2; ++i) {
                int idx = tid + i * 128, r = idx >> 2, c = idx & 3;
                cpa16(qs0 + SOFF(r, c), &g_qh[(size_t)(qbase + r) * DM + h * HD + c * 8]);
            }
            {
                const int jb = jbase + t_lo * BNO;
                const uint32_t kb = ks0 + (uint32_t)(t_lo & 1) * KVB;
                const uint32_t vb = vs0 + (uint32_t)(t_lo & 1) * KVB;
#pragma unroll
                for (int i = 0; i < 4; ++i) {
                    int idx = tid + i * 128, r = idx >> 2, c = idx & 3;
                    cpa16(kb + SOFF(r, c), &g_kh[(size_t)(jb + r) * DM + h * HD + c * 8]);
                    cpa16(vb + SOFF(r, c), &g_vh[(size_t)(jb + r) * DM + h * HD + c * 8]);
                }
                cpa_commit();
            }
            {
                const int jb = jbase + tp1 * BNO;
                const uint32_t kb = ks0 + (uint32_t)((t_lo + 1) & 1) * KVB;
                const uint32_t vb = vs0 + (uint32_t)((t_lo + 1) & 1) * KVB;
#pragma unroll
                for (int i = 0; i < 4; ++i) {
                    int idx = tid + i * 128, r = idx >> 2, c = idx & 3;
                    cpa16(kb + SOFF(r, c), &g_kh[(size_t)(jb + r) * DM + h * HD + c * 8]);
                    cpa16(vb + SOFF(r, c), &g_vh[(size_t)(jb + r) * DM + h * HD + c * 8]);
                }
                cpa_commit();
            }
        }
        cpa_wait1();
        __syncthreads();

        uint32_t qf[2][4];
#pragma unroll
        for (int kk = 0; kk < 2; ++kk) ldsm4(qf[kk], qs0 + offQ[kk]);

        const float ai0   = (float)(qbase + w * 16 + mg) * 0.01f;
        const float dbase = ai0 - (float)(jbase + 2 * mt) * 0.01f;

        for (int t = t_lo; t <= t_hi; ++t) {
            const uint32_t kbB = ks0 + (uint32_t)(t & 1) * KVB;
            const uint32_t vbB = vs0 + (uint32_t)(t & 1) * KVB;

#pragma unroll
            for (int hh = 0; hh < 2; ++hh) {
                // per-64-key-half clip at window boundaries (block-uniform)
                {
                    int jbh = jbase + t * BNO + hh * 64;
                    int d1 = jbh - (qbase + BM - 1);
                    int d2 = qbase - (jbh + 63);
                    int mind = d1 > d2 ? d1 : d2;
                    if (mind > 0 && (float)mind * dwv > DCUT) continue;
                }
                const uint32_t kb = kbB + (uint32_t)hh * 4096;
                const uint32_t vb = vbB + (uint32_t)hh * 4096;

                // ---- S = Q @ K^T
                float S[8][4];
#pragma unroll
                for (int c = 0; c < 8; ++c)
#pragma unroll
                    for (int r = 0; r < 4; ++r) S[c][r] = 0.f;

                uint32_t kf[4][2][4];
#pragma unroll
                for (int p = 0; p < 4; ++p)
#pragma unroll
                    for (int kk = 0; kk < 2; ++kk) ldsm4(kf[p][kk], kb + offK[p][kk]);
#pragma unroll
                for (int p = 0; p < 4; ++p)
#pragma unroll
                    for (int s2 = 0; s2 < 2; ++s2)
#pragma unroll
                        for (int kk = 0; kk < 2; ++kk)
                            mma_f16(S[2 * p + s2], qf[kk][0], qf[kk][1], qf[kk][2], qf[kk][3],
                                    kf[p][kk][2 * s2], kf[p][kk][2 * s2 + 1]);

                // ---- hoisted V loads (kc=0,1): LDSM latency overlaps softmax
                uint32_t vf[4][2][4];
#pragma unroll
                for (int kc = 0; kc < 2; ++kc)
#pragma unroll
                    for (int dp = 0; dp < 2; ++dp) ldsm4t(vf[kc][dp], vb + offV[kc][dp]);

                // ---- p = ex2(S + nC2*|ai-aj|) via ex2.approx.f16x2
                uint32_t pp[8][2];
                const float dt = dbase - (float)t * 1.28f - (float)hh * 0.64f;
#pragma unroll
                for (int c = 0; c < 8; ++c) {
                    float d00 = dt - 0.08f * (float)c;
                    float d01 = d00 - 0.01f;
                    float d10 = d00 + 0.08f;
                    float d11 = d00 + 0.07f;
                    float a00 = fmaf(nC2, fabsf(d00), S[c][0]);
                    float a01 = fmaf(nC2, fabsf(d01), S[c][1]);
                    float a10 = fmaf(nC2, fabsf(d10), S[c][2]);
                    float a11 = fmaf(nC2, fabsf(d11), S[c][3]);
                    pp[c][0] = ex2_h2(pack_f16x2(a00, a01));
                    pp[c][1] = ex2_h2(pack_f16x2(a10, a11));
                }

                // ---- l += P @ ones
#pragma unroll
                for (int kc = 0; kc < 4; ++kc)
                    mma_f16(lC, pp[2 * kc][0], pp[2 * kc][1], pp[2 * kc + 1][0], pp[2 * kc + 1][1],
                            ONE2, ONE2);

                // ---- remaining V loads (kc=2,3), then O += P @ V
#pragma unroll
                for (int kc = 2; kc < 4; ++kc)
#pragma unroll
                    for (int dp = 0; dp < 2; ++dp) ldsm4t(vf[kc][dp], vb + offV[kc][dp]);
#pragma unroll
                for (int kc = 0; kc < 4; ++kc)
#pragma unroll
                    for (int nt = 0; nt < 4; ++nt)
                        mma_f16(O[nt], pp[2 * kc][0], pp[2 * kc][1], pp[2 * kc + 1][0], pp[2 * kc + 1][1],
                                vf[kc][nt >> 1][2 * (nt & 1)], vf[kc][nt >> 1][2 * (nt & 1) + 1]);
            }

            __syncthreads();   // all warps done with buffer (t&1)

            // ---- prefetch tile t+2 into buffer (t&1)
            if (t + 2 <= t_hi) {
                const int jb2 = jbase + (t + 2) * BNO;
                const uint32_t kb2 = ks0 + (uint32_t)(t & 1) * KVB;
                const uint32_t vb2 = vs0 + (uint32_t)(t & 1) * KVB;
#pragma unroll
                for (int i = 0; i < 4; ++i) {
                    int idx = tid + i * 128, r = idx >> 2, c = idx & 3;
                    cpa16(kb2 + SOFF(r, c), &g_kh[(size_t)(jb2 + r) * DM + h * HD + c * 8]);
                    cpa16(vb2 + SOFF(r, c), &g_vh[(size_t)(jb2 + r) * DM + h * HD + c * 8]);
                }
            }
            cpa_commit();
            if (t < t_hi) {
                cpa_wait1();
                __syncthreads();
            }
        }
    }

    // ---- epilogue: write fp16 partials (zeros if window empty)
    const int i0 = qbase + w * 16 + mg;
    const int i1 = i0 + 8;
    if (mt == 0) {
        g_lp[sl][i0 * NH + h] = lC[0];
        g_lp[sl][i1 * NH + h] = lC[2];
    }
    __half* oB = &g_attp[sl][0];
#pragma unroll
    for (int nt = 0; nt < 4; ++nt) {
        int d = nt * 8 + 2 * mt;
        *(__half2*)&oB[(size_t)i0 * DM + h * HD + d] = __floats2half2_rn(O[nt][0], O[nt][1]);
        *(__half2*)&oB[(size_t)i1 * DM + h * HD + d] = __floats2half2_rn(O[nt][2], O[nt][3]);
    }
}

// ---------------------------------------------------------------------------
// Output projection with FUSED combine (fp16 mma.sync), BM=32, grid 192.
// All combine loads (3 slices x 4 stages + lp) hoisted to kernel entry into
// registers (MLP ~24/thread), so stage fills are pure compute + STS.
// ---------------------------------------------------------------------------
__global__ __launch_bounds__(128, 4) void gemm_out_tc(
    const float* __restrict__ bo, float* __restrict__ out)
{
    __shared__ __align__(16) __half As[2][32 * 32];
    __shared__ __align__(16) __half Bs[2][128 * 32];

    const int tid = threadIdx.x, lane = tid & 31, w = tid >> 5;
    const int wm = w & 1, wn = w >> 1;
    const int m0 = blockIdx.x * 32;

    const int lg = lane >> 3, lr = lane & 7;
    const int mg = lane >> 2, mt = lane & 3;

    const uint32_t bs0 = (uint32_t)__cvta_generic_to_shared(Bs);
    const uint32_t BBUF = 128 * 32 * 2;

    // ---- hoisted combine loads: everything this thread will ever read
    const int rA = tid >> 2, cA = tid & 3;
    const int mA = m0 + rA;
    uint4 tvR[4][NSLICE];
    float lpR[4][NSLICE];
#pragma unroll
    for (int st = 0; st < 4; ++st)
#pragma unroll
        for (int s2 = 0; s2 < NSLICE; ++s2) {
            tvR[st][s2] = ldg128(&g_attp[s2][(size_t)mA * DM + st * 32 + cA * 8]);
            lpR[st][s2] = g_lp[s2][mA * NH + st];
        }

    // fill A tile (32x32) for k-stage st into buffer b: pure compute + STS
    auto fillA = [&](int st, int b) {
        float acc[8] = {0.f, 0.f, 0.f, 0.f, 0.f, 0.f, 0.f, 0.f};
        float lsum = 0.f;
#pragma unroll
        for (int s2 = 0; s2 < NSLICE; ++s2) {
            uint4 tv = tvR[st][s2];
            float2 f0 = __half22float2(*(__half2*)&tv.x);
            float2 f1 = __half22float2(*(__half2*)&tv.y);
            float2 f2 = __half22float2(*(__half2*)&tv.z);
            float2 f3 = __half22float2(*(__half2*)&tv.w);
            acc[0] += f0.x; acc[1] += f0.y; acc[2] += f1.x; acc[3] += f1.y;
            acc[4] += f2.x; acc[5] += f2.y; acc[6] += f3.x; acc[7] += f3.y;
            lsum += lpR[st][s2];
        }
        float inv = 1.0f / lsum;
        __half2 h0 = __floats2half2_rn(acc[0] * inv, acc[1] * inv);
        __half2 h1 = __floats2half2_rn(acc[2] * inv, acc[3] * inv);
        __half2 h2 = __floats2half2_rn(acc[4] * inv, acc[5] * inv);
        __half2 h3 = __floats2half2_rn(acc[6] * inv, acc[7] * inv);
        uint4 pk = make_uint4(*(uint32_t*)&h0, *(uint32_t*)&h1,
                              *(uint32_t*)&h2, *(uint32_t*)&h3);
        *(uint4*)((char*)As + (size_t)b * (32 * 32 * 2) + SOFF(rA, cA)) = pk;
    };

    // prologue: A stages 0,1 (register combine); B stages 0,1 (cp.async)
#pragma unroll
    for (int s = 0; s < 2; ++s) {
#pragma unroll
        for (int r = 0; r < 4; ++r) {
            int id = tid + r * 128;
            int row = id >> 2, c = id & 3;
            cpa16(bs0 + s * BBUF + SOFF(row, c), &g_woht[(size_t)row * DM + s * 32 + c * 8]);
        }
        cpa_commit();
    }
    fillA(0, 0);
    fillA(1, 1);

    float Cf[8][4];
#pragma unroll
    for (int f = 0; f < 8; ++f)
#pragma unroll
        for (int r = 0; r < 4; ++r) Cf[f][r] = 0.f;

    uint32_t offA[2], offB[4][2];
#pragma unroll
    for (int kk = 0; kk < 2; ++kk)
        offA[kk] = SOFF(wm * 16 + ((lg & 1) << 3) + lr, 2 * kk + (lg >> 1));
#pragma unroll
    for (int g = 0; g < 4; ++g)
#pragma unroll
        for (int kk = 0; kk < 2; ++kk)
            offB[g][kk] = SOFF(wn * 64 + g * 16 + ((lg >> 1) << 3) + lr, 2 * kk + (lg & 1));

    const uint32_t as0 = (uint32_t)__cvta_generic_to_shared(As);
    const uint32_t ABUF = 32 * 32 * 2;

#pragma unroll
    for (int s = 0; s < 4; ++s) {
        cpa_wait1();
        __syncthreads();          // B arrival + A STS visibility
        const uint32_t ab = as0 + (uint32_t)(s & 1) * ABUF;
        const uint32_t bb = bs0 + (uint32_t)(s & 1) * BBUF;
#pragma unroll
        for (int kk = 0; kk < 2; ++kk) {
            uint32_t af[4];
            ldsm4(af, ab + offA[kk]);
#pragma unroll
            for (int g = 0; g < 4; ++g) {
                uint32_t bf[4];
                ldsm4(bf, bb + offB[g][kk]);
                mma_f16(Cf[2 * g],     af[0], af[1], af[2], af[3], bf[0], bf[1]);
                mma_f16(Cf[2 * g + 1], af[0], af[1], af[2], af[3], bf[2], bf[3]);
            }
        }
        __syncthreads();          // buffer (s&1) fully consumed
        if (s + 2 < 4) {
            fillA(s + 2, s & 1);
            int k0 = (s + 2) * 32;
#pragma unroll
            for (int r = 0; r < 4; ++r) {
                int id = tid + r * 128;
                int row = id >> 2, c = id & 3;
                cpa16(bb + SOFF(row, c), &g_woht[(size_t)row * DM + k0 + c * 8]);
            }
        }
        cpa_commit();
    }

    const int mr0 = m0 + wm * 16 + mg;
    const int mr1 = mr0 + 8;
#pragma unroll
    for (int g = 0; g < 4; ++g)
#pragma unroll
        for (int s2 = 0; s2 < 2; ++s2) {
            int n = wn * 64 + g * 16 + s2 * 8 + 2 * mt;
            float b0 = bo[n], b1 = bo[n + 1];
            float* d = Cf[2 * g + s2];
            *(float2*)&out[(size_t)mr0 * DM + n] = make_float2(d[0] + b0, d[1] + b1);
            *(float2*)&out[(size_t)mr1 * DM + n] = make_float2(d[2] + b0, d[3] + b1);
        }
}

// ---------------------------------------------------------------------------
extern "C" void kernel_launch(void* const* d_in, const int* in_sizes, int n_in,
                              void* d_out, int out_size)
{
    const float* x  = (const float*)d_in[0];
    const float* Wq = (const float*)d_in[1];
    const float* bq = (const float*)d_in[2];
    const float* Wk = (const float*)d_in[3];
    const float* bk = (const float*)d_in[4];
    const float* Wv = (const float*)d_in[5];
    const float* bv = (const float*)d_in[6];
    const float* Wo = (const float*)d_in[7];
    const float* bo = (const float*)d_in[8];
    const float* dw = (const float*)d_in[9];
    float* out = (float*)d_out;

    convert_kernel<<<1600, 256>>>(x, Wq, Wk, Wv, Wo);
    gemm_qkv_tc<<<dim3(NT / 128, 3, 1), 256>>>(bq, bk, bv);
    attn_kernel<<<dim3(NT / BM, NH, NSLICE), 128>>>(dw);
    gemm_out_tc<<<NT / 32, 128>>>(bo, out);
}